// round 2
// baseline (speedup 1.0000x reference)
#include <cuda_runtime.h>
#include <cuda_bf16.h>
#include <math.h>

// WaveNet — bf16x3 split tensor-core version (mma.sync.m16n8k16, fp32 accum).
// Each fp32 operand x is split hi=bf16(x), lo=bf16(x-hi); product computed as
// hi*hi + hi*lo + lo*hi (3 mmas), error ~2^-18. hi/lo packed in one 32-bit
// smem word per element; smem laid out in "fragment order" so each thread's
// mma fragment is one contiguous LDS.128.

#define HS 65536            // h row stride (time)
#define TT 128              // time tile
#define TOUT 63489          // T - 2048 + 1
#define NLAYER 20

__device__ float g_h[2][64 * HS];     // 2 x 16 MB (L2-resident ping-pong)
__device__ float g_skip[64 * TOUT];   // 16.2 MB

// ---------------------------------------------------------------------------
__device__ __forceinline__ unsigned pack_hl(float x) {
    __nv_bfloat16 h = __float2bfloat16(x);
    float hf = __bfloat162float(h);
    __nv_bfloat16 l = __float2bfloat16(x - hf);
    return (unsigned)__bfloat16_as_ushort(h) |
           ((unsigned)__bfloat16_as_ushort(l) << 16);
}

// A operand (M x K), fragment order for m16n8k16: tile (m/16, k/16) is 256
// contiguous words; within tile, lane's 8 words are contiguous.
__device__ __forceinline__ int addrA(int m, int k, int kt16) {
    int lane = ((m & 7) << 2) | ((k >> 1) & 3);
    int w = (k & 1) | (((m >> 3) & 1) << 1) | (((k >> 3) & 1) << 2);
    return ((((m >> 4) * kt16 + (k >> 4)) << 8) + (lane << 3) + w);
}
// B operand (K x N=TT): tile (k/16, t/8) is 128 contiguous words; lane's 4
// words contiguous.
__device__ __forceinline__ int addrB(int k, int t) {
    int lane = ((t & 7) << 2) | ((k >> 1) & 3);
    int w = (k & 1) | (((k >> 3) & 1) << 1);
    return ((((k >> 4) * (TT >> 3) + (t >> 3)) << 7) + (lane << 2) + w);
}

__device__ __forceinline__ void mma_bf(float* d, const unsigned* a, const unsigned* b) {
    asm volatile(
        "mma.sync.aligned.m16n8k16.row.col.f32.bf16.bf16.f32 "
        "{%0,%1,%2,%3},{%4,%5,%6,%7},{%8,%9},{%0,%1,%2,%3};\n"
        : "+f"(d[0]), "+f"(d[1]), "+f"(d[2]), "+f"(d[3])
        : "r"(a[0]), "r"(a[1]), "r"(a[2]), "r"(a[3]), "r"(b[0]), "r"(b[1]));
}

__device__ __forceinline__ void loadA(const unsigned* s, int mtile, int kc,
                                      int kt16, int lane,
                                      unsigned* Ah, unsigned* Al) {
    const uint4* p = (const uint4*)(s + (((mtile * kt16 + kc) << 8) + (lane << 3)));
    uint4 q0 = p[0], q1 = p[1];
    Ah[0] = __byte_perm(q0.x, q0.y, 0x5410); Al[0] = __byte_perm(q0.x, q0.y, 0x7632);
    Ah[1] = __byte_perm(q0.z, q0.w, 0x5410); Al[1] = __byte_perm(q0.z, q0.w, 0x7632);
    Ah[2] = __byte_perm(q1.x, q1.y, 0x5410); Al[2] = __byte_perm(q1.x, q1.y, 0x7632);
    Ah[3] = __byte_perm(q1.z, q1.w, 0x5410); Al[3] = __byte_perm(q1.z, q1.w, 0x7632);
}
__device__ __forceinline__ void loadB(const unsigned* s, int kc, int ntile,
                                      int lane, unsigned* Bh, unsigned* Bl) {
    const uint4* p = (const uint4*)(s + (((kc * (TT >> 3) + ntile) << 7) + (lane << 2)));
    uint4 q = *p;
    Bh[0] = __byte_perm(q.x, q.y, 0x5410); Bl[0] = __byte_perm(q.x, q.y, 0x7632);
    Bh[1] = __byte_perm(q.z, q.w, 0x5410); Bl[1] = __byte_perm(q.z, q.w, 0x7632);
}

__device__ __forceinline__ float fast_tanh(float x) {
    float e = __expf(-2.0f * fabsf(x));
    float r = __fdividef(1.0f - e, 1.0f + e);
    return copysignf(r, x);
}
__device__ __forceinline__ float fast_sig(float x) {
    return __fdividef(1.0f, 1.0f + __expf(-x));
}

// ---------------------------------------------------------------------------
__global__ void init_kernel(const float* __restrict__ input,
                            const float* __restrict__ w0,
                            const float* __restrict__ b0) {
    int stride = gridDim.x * blockDim.x;
    for (int idx = blockIdx.x * blockDim.x + threadIdx.x; idx < 64 * HS; idx += stride) {
        int c = idx >> 16;
        int t = idx & (HS - 1);
        g_h[0][idx] = w0[c] * input[t] + b0[c];
    }
    for (int idx = blockIdx.x * blockDim.x + threadIdx.x; idx < 64 * TOUT; idx += stride) {
        g_skip[idx] = 0.0f;
    }
}

// ---------------------------------------------------------------------------
// One dilated layer (tensor-core).
// smem (words): sW1[16384] | sW2[8192] | sX[16384] (reused as fp32 sF) | sZ[8192]
__global__ void __launch_bounds__(512, 1) layer_kernel(
    const float* __restrict__ wf, const float* __restrict__ wg,
    const float* __restrict__ wr, const float* __restrict__ ws,
    const float* __restrict__ bf, const float* __restrict__ bg,
    const float* __restrict__ br, const float* __restrict__ bs,
    int inbuf, int W, int d, int skip_shift)
{
    extern __shared__ unsigned smem[];
    unsigned* sW1 = smem;                // 128x128 A-frag packed
    unsigned* sW2 = smem + 16384;        // 128x64  A-frag packed
    unsigned* sX  = smem + 24576;        // 128xTT  B-frag packed
    unsigned* sZ  = smem + 40960;        // 64xTT   B-frag packed
    float* sF = (float*)sX;              // fp32 activations (reuse)

    const float* __restrict__ hin = g_h[inbuf];
    float* __restrict__ hout = g_h[1 - inbuf];
    const int tid = threadIdx.x;
    const int lane = tid & 31;
    const int wrp = tid >> 5;
    const int wm = wrp >> 2, wn = wrp & 3;
    const int m0 = wm * 32, n0 = wn * 32;

    // Stage weights in fragment order (once per CTA).
    for (int idx = tid; idx < 128 * 128; idx += 512) {
        int k = idx >> 7, m = idx & 127;
        int c = k & 63, lr = k >> 6;
        float v = (m < 64) ? wf[(m * 64 + c) * 2 + lr]
                           : wg[((m - 64) * 64 + c) * 2 + lr];
        sW1[addrA(m, k, 8)] = pack_hl(v);
    }
    for (int idx = tid; idx < 128 * 64; idx += 512) {
        int k = idx >> 7, m = idx & 127;   // k in [0,64)
        float v = (m < 64) ? wr[m * 64 + k] : ws[(m - 64) * 64 + k];
        sW2[addrA(m, k, 4)] = pack_hl(v);
    }
    __syncthreads();

    const int Wout = W - d;
    const int ntiles = (Wout + TT - 1) / TT;

    for (int tile = blockIdx.x; tile < ntiles; tile += gridDim.x) {
        const int t0 = tile * TT;

        // Stage X = [left; right] packed in B-frag order.
        for (int idx = tid; idx < 128 * TT; idx += 512) {
            int k = idx >> 7, t = idx & (TT - 1);
            int c = k & 63;
            int lt = t0 + t;
            float v = 0.0f;
            if (lt < Wout) v = hin[c * HS + lt + ((k >= 64) ? d : 0)];
            sX[addrB(k, t)] = pack_hl(v);
        }
        __syncthreads();

        // GEMM1: 128 x TT, K=128 (8 chunks of 16)
        float acc[2][4][4];
        #pragma unroll
        for (int a = 0; a < 2; a++)
            #pragma unroll
            for (int b = 0; b < 4; b++)
                #pragma unroll
                for (int r = 0; r < 4; r++) acc[a][b][r] = 0.0f;

        #pragma unroll
        for (int kc = 0; kc < 8; kc++) {
            unsigned Ah[2][4], Al[2][4], Bh[4][2], Bl[4][2];
            loadA(sW1, (m0 >> 4),     kc, 8, lane, Ah[0], Al[0]);
            loadA(sW1, (m0 >> 4) + 1, kc, 8, lane, Ah[1], Al[1]);
            #pragma unroll
            for (int nt = 0; nt < 4; nt++)
                loadB(sX, kc, (n0 >> 3) + nt, lane, Bh[nt], Bl[nt]);
            #pragma unroll
            for (int mt = 0; mt < 2; mt++)
                #pragma unroll
                for (int nt = 0; nt < 4; nt++) {
                    mma_bf(acc[mt][nt], Ah[mt], Bh[nt]);
                    mma_bf(acc[mt][nt], Ah[mt], Bl[nt]);
                    mma_bf(acc[mt][nt], Al[mt], Bh[nt]);
                }
        }
        __syncthreads();   // all sX reads done

        // Activations -> sF (fp32, reuses sX region)
        #pragma unroll
        for (int mt = 0; mt < 2; mt++) {
            int mbase = m0 + mt * 16 + (lane >> 2);
            #pragma unroll
            for (int nt = 0; nt < 4; nt++) {
                int tb = n0 + nt * 8 + ((lane & 3) << 1);
                #pragma unroll
                for (int r = 0; r < 4; r++) {
                    int m = mbase + ((r & 2) ? 8 : 0);
                    int t = tb + (r & 1);
                    float v = acc[mt][nt][r];
                    v = (m < 64) ? fast_tanh(v + bf[m])
                                 : fast_sig(v + bg[m - 64]);
                    sF[m * TT + t] = v;
                }
            }
        }
        __syncthreads();

        // z = tanh(f)*sig(g), packed into sZ (B-frag order)
        for (int idx = tid; idx < 64 * TT; idx += 512) {
            int c = idx >> 7, t = idx & (TT - 1);
            float z = sF[c * TT + t] * sF[(c + 64) * TT + t];
            sZ[addrB(c, t)] = pack_hl(z);
        }
        __syncthreads();

        // GEMM2: 128 x TT, K=64 (4 chunks)
        float acc2[2][4][4];
        #pragma unroll
        for (int a = 0; a < 2; a++)
            #pragma unroll
            for (int b = 0; b < 4; b++)
                #pragma unroll
                for (int r = 0; r < 4; r++) acc2[a][b][r] = 0.0f;

        #pragma unroll
        for (int kc = 0; kc < 4; kc++) {
            unsigned Ah[2][4], Al[2][4], Bh[4][2], Bl[4][2];
            loadA(sW2, (m0 >> 4),     kc, 4, lane, Ah[0], Al[0]);
            loadA(sW2, (m0 >> 4) + 1, kc, 4, lane, Ah[1], Al[1]);
            #pragma unroll
            for (int nt = 0; nt < 4; nt++)
                loadB(sZ, kc, (n0 >> 3) + nt, lane, Bh[nt], Bl[nt]);
            #pragma unroll
            for (int mt = 0; mt < 2; mt++)
                #pragma unroll
                for (int nt = 0; nt < 4; nt++) {
                    mma_bf(acc2[mt][nt], Ah[mt], Bh[nt]);
                    mma_bf(acc2[mt][nt], Ah[mt], Bl[nt]);
                    mma_bf(acc2[mt][nt], Al[mt], Bh[nt]);
                }
        }

        // Epilogue
        #pragma unroll
        for (int mt = 0; mt < 2; mt++) {
            int mbase = m0 + mt * 16 + (lane >> 2);
            #pragma unroll
            for (int nt = 0; nt < 4; nt++) {
                int tb = n0 + nt * 8 + ((lane & 3) << 1);
                #pragma unroll
                for (int r = 0; r < 4; r++) {
                    int m = mbase + ((r & 2) ? 8 : 0);
                    int gt = t0 + tb + (r & 1);
                    float v = acc2[mt][nt][r];
                    if (m < 64) {
                        if (gt < Wout)
                            hout[m * HS + gt] = v + br[m] + hin[m * HS + gt + d];
                    } else {
                        int gc = gt - skip_shift;
                        if (gt < Wout && gc >= 0 && gc < TOUT)
                            g_skip[(m - 64) * TOUT + gc] += v + bs[m - 64];
                    }
                }
            }
        }
        __syncthreads();
    }
}

// ---------------------------------------------------------------------------
// Output head, same bf16x3 machinery.
// smem (words): sW0[4096] | sW1o[16384] | sB0[8192] | sB1[8192]
__global__ void __launch_bounds__(512, 1) final_kernel(
    const float* __restrict__ alpha,
    const float* __restrict__ w_out0, const float* __restrict__ b_out0,
    const float* __restrict__ w_out1, const float* __restrict__ b_out1,
    float* __restrict__ out)
{
    extern __shared__ unsigned smem[];
    unsigned* sW0  = smem;            // 64x64   A-frag
    unsigned* sW1o = smem + 4096;     // 256x64  A-frag
    unsigned* sB0  = smem + 20480;    // 64xTT   B-frag (skip act)
    unsigned* sB1  = smem + 28672;    // 64xTT   B-frag (mid act)

    const int tid = threadIdx.x, lane = tid & 31, wrp = tid >> 5;
    const int wm = wrp >> 2, wn = wrp & 3;
    const int n0 = wn * 32;

    for (int idx = tid; idx < 64 * 64; idx += 512) {
        int m = idx >> 6, k = idx & 63;
        sW0[addrA(m, k, 4)] = pack_hl(w_out0[m * 64 + k]);
    }
    for (int idx = tid; idx < 256 * 64; idx += 512) {
        int m = idx >> 6, k = idx & 63;
        sW1o[addrA(m, k, 4)] = pack_hl(w_out1[m * 64 + k]);
    }
    __syncthreads();

    const int ntiles = (TOUT + TT - 1) / TT;
    for (int tile = blockIdx.x; tile < ntiles; tile += gridDim.x) {
        const int t0 = tile * TT;

        // Stage skip tile with leaky-relu(alpha0), packed B-frag.
        for (int idx = tid; idx < 64 * TT; idx += 512) {
            int c = idx >> 7, t = idx & (TT - 1);
            int gt = t0 + t;
            float v = (gt < TOUT) ? g_skip[c * TOUT + gt] : 0.0f;
            v = (v > 0.0f) ? v : alpha[c] * v;
            sB0[addrB(c, t)] = pack_hl(v);
        }
        __syncthreads();

        // GEMM0: 64 x TT, K=64. warp tile 16x32 (mtile = wm).
        float acc0[4][4];
        #pragma unroll
        for (int b = 0; b < 4; b++)
            #pragma unroll
            for (int r = 0; r < 4; r++) acc0[b][r] = 0.0f;

        #pragma unroll
        for (int kc = 0; kc < 4; kc++) {
            unsigned Ah[4], Al[4], Bh[4][2], Bl[4][2];
            loadA(sW0, wm, kc, 4, lane, Ah, Al);
            #pragma unroll
            for (int nt = 0; nt < 4; nt++)
                loadB(sB0, kc, (n0 >> 3) + nt, lane, Bh[nt], Bl[nt]);
            #pragma unroll
            for (int nt = 0; nt < 4; nt++) {
                mma_bf(acc0[nt], Ah, Bh[nt]);
                mma_bf(acc0[nt], Ah, Bl[nt]);
                mma_bf(acc0[nt], Al, Bh[nt]);
            }
        }
        // bias + lrelu(alpha1), pack directly into sB1 (disjoint from sB0)
        #pragma unroll
        for (int nt = 0; nt < 4; nt++) {
            int tb = n0 + nt * 8 + ((lane & 3) << 1);
            #pragma unroll
            for (int r = 0; r < 4; r++) {
                int m = wm * 16 + (lane >> 2) + ((r & 2) ? 8 : 0);
                int t = tb + (r & 1);
                float v = acc0[nt][r] + b_out0[m];
                v = (v > 0.0f) ? v : alpha[64 + m] * v;
                sB1[addrB(m, t)] = pack_hl(v);
            }
        }
        __syncthreads();

        // GEMM1: 256 x TT, K=64. warp tile 64x32 (mtiles wm*4..wm*4+3).
        float acc1[4][4][4];
        #pragma unroll
        for (int a = 0; a < 4; a++)
            #pragma unroll
            for (int b = 0; b < 4; b++)
                #pragma unroll
                for (int r = 0; r < 4; r++) acc1[a][b][r] = 0.0f;

        #pragma unroll
        for (int kc = 0; kc < 4; kc++) {
            unsigned Ah[4][4], Al[4][4], Bh[4][2], Bl[4][2];
            #pragma unroll
            for (int mt = 0; mt < 4; mt++)
                loadA(sW1o, wm * 4 + mt, kc, 4, lane, Ah[mt], Al[mt]);
            #pragma unroll
            for (int nt = 0; nt < 4; nt++)
                loadB(sB1, kc, (n0 >> 3) + nt, lane, Bh[nt], Bl[nt]);
            #pragma unroll
            for (int mt = 0; mt < 4; mt++)
                #pragma unroll
                for (int nt = 0; nt < 4; nt++) {
                    mma_bf(acc1[mt][nt], Ah[mt], Bh[nt]);
                    mma_bf(acc1[mt][nt], Ah[mt], Bl[nt]);
                    mma_bf(acc1[mt][nt], Al[mt], Bh[nt]);
                }
        }
        #pragma unroll
        for (int mt = 0; mt < 4; mt++) {
            int mbase = wm * 64 + mt * 16 + (lane >> 2);
            #pragma unroll
            for (int nt = 0; nt < 4; nt++) {
                int tb = n0 + nt * 8 + ((lane & 3) << 1);
                #pragma unroll
                for (int r = 0; r < 4; r++) {
                    int m = mbase + ((r & 2) ? 8 : 0);
                    int gt = t0 + tb + (r & 1);
                    if (gt < TOUT)
                        out[m * TOUT + gt] = acc1[mt][nt][r] + b_out1[m];
                }
            }
        }
        __syncthreads();
    }
}

// ---------------------------------------------------------------------------
extern "C" void kernel_launch(void* const* d_in, const int* in_sizes, int n_in,
                              void* d_out, int out_size) {
    const float* input  = (const float*)d_in[0];
    const float* w0     = (const float*)d_in[1];
    const float* b0     = (const float*)d_in[2];
    const float* wf     = (const float*)d_in[3];
    const float* bf     = (const float*)d_in[4];
    const float* wg     = (const float*)d_in[5];
    const float* bg     = (const float*)d_in[6];
    const float* wr     = (const float*)d_in[7];
    const float* br     = (const float*)d_in[8];
    const float* ws     = (const float*)d_in[9];
    const float* bs     = (const float*)d_in[10];
    const float* alpha  = (const float*)d_in[11];
    const float* w_out0 = (const float*)d_in[12];
    const float* b_out0 = (const float*)d_in[13];
    const float* w_out1 = (const float*)d_in[14];
    const float* b_out1 = (const float*)d_in[15];

    const int SMEM_LAYER = 49152 * 4;   // 192 KB
    const int SMEM_FINAL = 36864 * 4;   // 144 KB
    cudaFuncSetAttribute(layer_kernel, cudaFuncAttributeMaxDynamicSharedMemorySize, SMEM_LAYER);
    cudaFuncSetAttribute(final_kernel, cudaFuncAttributeMaxDynamicSharedMemorySize, SMEM_FINAL);

    init_kernel<<<512, 256>>>(input, w0, b0);

    int W = HS;
    int offset = 2048;
    int buf = 0;
    for (int i = 0; i < NLAYER; i++) {
        int d = 1 << (i % 10);
        offset -= d;
        layer_kernel<<<148, 512, SMEM_LAYER>>>(
            wf + i * 64 * 64 * 2, wg + i * 64 * 64 * 2,
            wr + i * 64 * 64,     ws + i * 64 * 64,
            bf + i * 64, bg + i * 64, br + i * 64, bs + i * 64,
            buf, W, d, offset - 1);
        W -= d;
        buf ^= 1;
    }

    final_kernel<<<148, 512, SMEM_FINAL>>>(alpha, w_out0, b_out0, w_out1, b_out1,
                                           (float*)d_out);
}